// round 11
// baseline (speedup 1.0000x reference)
#include <cuda_runtime.h>
#include <cuda_fp16.h>

#define NB    50
#define HID   32
#define HALFD 16
#define JJ    16         // HID/2 packed pairs
#define VSTH  17         // u32 stride per bucket row (odd -> <=2-way conflicts)
#define W2ST  17         // padded W2 row stride in smem
#define TPB   256
#define CR    3          // rows per thread per chunk
#define CHROWS (TPB * CR)   // 768 rows per chunk
#define NBLK  888        // 148 SMs x 6 blocks -> persistent, exactly resident

__device__ __forceinline__ unsigned long long pack2(float lo, float hi) {
    unsigned long long r;
    asm("mov.b64 %0, {%1, %2};" : "=l"(r) : "f"(lo), "f"(hi));
    return r;
}
__device__ __forceinline__ unsigned long long fma2(unsigned long long a,
                                                   unsigned long long b,
                                                   unsigned long long c) {
    unsigned long long d;
    asm("fma.rn.f32x2 %0, %1, %2, %3;" : "=l"(d) : "l"(a), "l"(b), "l"(c));
    return d;
}
__device__ __forceinline__ void unpack2(unsigned long long v, float& lo, float& hi) {
    asm("mov.b64 {%0, %1}, %2;" : "=f"(lo), "=f"(hi) : "l"(v));
}

__global__ __launch_bounds__(TPB, 6)
void lightwin_kernel(const float2* __restrict__ x, const int* __restrict__ buckets,
                     const float* __restrict__ W1, const float* __restrict__ b1,
                     const float* __restrict__ W2, const float* __restrict__ b2v,
                     const float* __restrict__ Wh, const float* __restrict__ bh,
                     float* __restrict__ out, int B, int nchunks) {
    __shared__ __align__(16) float sAB[HID * 2];     // W1 row0 | W1 row1
    __shared__ __align__(16) float sC[HID];          // b1
    __shared__ unsigned sVh[NB * VSTH];              // V = Wh @ W2^T, half2 pairs
    __shared__ float sc[NB];                         // c[b] = bh[b] + b2 . Wh[b]
    // staging for fused precompute (coalesced loads; bank-aware strides)
    __shared__ float sW2[HID * W2ST];
    __shared__ float sWh[NB * HALFD];
    __shared__ float sB2[HALFD];
    __shared__ float sBh[NB];

    int tid = threadIdx.x;

    // ---- stage 1: coalesced global -> smem (paid once per persistent block)
    if (tid < HID * 2)     sAB[tid] = W1[tid];
    if (tid < HID)         sC[tid]  = b1[tid];
    for (int i = tid; i < HID * HALFD; i += TPB)
        sW2[(i >> 4) * W2ST + (i & 15)] = W2[i];
    for (int i = tid; i < NB * HALFD; i += TPB)
        sWh[i] = Wh[i];
    if (tid < HALFD)       sB2[tid] = b2v[tid];
    if (tid < NB)          sBh[tid] = bh[tid];
    __syncthreads();

    // ---- stage 2: combined head weights V (half2) + folded bias c
    for (int e = tid; e < NB * JJ; e += TPB) {
        int b = e >> 4, jj = e & 15;
        const float* whp = &sWh[b * HALFD];
        const float* wa  = &sW2[(2 * jj)     * W2ST];
        const float* wb  = &sW2[(2 * jj + 1) * W2ST];
        float s0 = 0.f, s1 = 0.f;
        #pragma unroll
        for (int k = 0; k < HALFD; k++) {
            float wh = whp[k];
            s0 = fmaf(wa[k], wh, s0);
            s1 = fmaf(wb[k], wh, s1);
        }
        __half2 h = __floats2half2_rn(s0, s1);
        sVh[b * VSTH + jj] = *reinterpret_cast<unsigned*>(&h);
    }
    for (int b = tid; b < NB; b += TPB) {
        float s = sBh[b];
        #pragma unroll
        for (int k = 0; k < HALFD; k++)
            s = fmaf(sB2[k], sWh[b * HALFD + k], s);
        sc[b] = s;
    }
    __syncthreads();

    // ---- stage 3: persistent block-stride loop over 768-row chunks
    for (int ch = blockIdx.x; ch < nchunks; ch += NBLK) {
        int base = ch * CHROWS + tid;

        unsigned long long x0d[CR], x1d[CR];
        float acc0[CR], acc1[CR];
        int   va[CR];

        #pragma unroll
        for (int r = 0; r < CR; r++) {
            int idx = base + r * TPB;
            bool p = idx < B;
            float2 xv = p ? __ldg(&x[idx]) : make_float2(0.f, 0.f);
            int b = p ? buckets[idx] : 0;
            b = ((unsigned)b < NB) ? b : (NB - 1);
            va[r]   = b * VSTH;
            x0d[r]  = pack2(xv.x, xv.x);
            x1d[r]  = pack2(xv.y, xv.y);
            acc0[r] = sc[b];           // head bias folded into accumulator
            acc1[r] = 0.f;
        }

        #pragma unroll
        for (int jj = 0; jj < JJ; jj++) {
            // warp-uniform weight pairs: broadcast LDS.64
            unsigned long long a2  = *(const unsigned long long*)&sAB[2 * jj];
            unsigned long long b2w = *(const unsigned long long*)&sAB[HID + 2 * jj];
            unsigned long long c2  = *(const unsigned long long*)&sC[2 * jj];
            #pragma unroll
            for (int r = 0; r < CR; r++) {
                unsigned long long z = fma2(x1d[r], b2w, c2);
                z = fma2(x0d[r], a2, z);
                float z0, z1;
                unpack2(z, z0, z1);
                float h0 = fmaxf(z0, 0.f);
                float h1 = fmaxf(z1, 0.f);
                unsigned vh = sVh[va[r] + jj];     // one LDS.32 = both fp16 weights
                float2 vf = __half22float2(*reinterpret_cast<__half2*>(&vh));
                acc0[r] = fmaf(h0, vf.x, acc0[r]);
                acc1[r] = fmaf(h1, vf.y, acc1[r]);
            }
        }

        #pragma unroll
        for (int r = 0; r < CR; r++) {
            int idx = base + r * TPB;
            if (idx < B) out[idx] = acc0[r] + acc1[r];
        }
    }
}

extern "C" void kernel_launch(void* const* d_in, const int* in_sizes, int n_in,
                              void* d_out, int out_size) {
    const float2* x     = (const float2*)d_in[0];
    const int* buckets  = (const int*)d_in[1];
    const float* W1     = (const float*)d_in[2];
    const float* b1     = (const float*)d_in[3];
    const float* W2     = (const float*)d_in[4];
    const float* b2v    = (const float*)d_in[5];
    const float* Wh     = (const float*)d_in[6];
    const float* bh     = (const float*)d_in[7];
    float* out          = (float*)d_out;

    int B = in_sizes[1];  // buckets element count = row count
    int nchunks = (B + CHROWS - 1) / CHROWS;   // 2605
    int grid = NBLK < nchunks ? NBLK : nchunks;
    lightwin_kernel<<<grid, TPB>>>(x, buckets, W1, b1, W2, b2v, Wh, bh, out, B, nchunks);
}

// round 12
// speedup vs baseline: 1.0125x; 1.0125x over previous
#include <cuda_runtime.h>
#include <cuda_fp16.h>

#define NB    50
#define HID   32
#define HALFD 16
#define JJ    16         // HID/2 packed pairs
#define VSTH  17         // u32 stride per bucket row (odd -> <=2-way conflicts)
#define W2ST  17         // padded W2 row stride in smem
#define TPB   256
#define CR    4          // rows per thread per chunk
#define CHROWS (TPB * CR)   // 1024 rows per chunk
#define NBLK  740        // 148 SMs x 5 blocks -> persistent, exactly resident

// Warp-uniform MLP weights in constant bank (LDCU path, off the LSU crossbar)
__constant__ float cW1[HID * 2];   // W1 row0 | W1 row1
__constant__ float cB1[HID];       // b1

__device__ __forceinline__ unsigned long long pack2(float lo, float hi) {
    unsigned long long r;
    asm("mov.b64 %0, {%1, %2};" : "=l"(r) : "f"(lo), "f"(hi));
    return r;
}
__device__ __forceinline__ unsigned long long fma2(unsigned long long a,
                                                   unsigned long long b,
                                                   unsigned long long c) {
    unsigned long long d;
    asm("fma.rn.f32x2 %0, %1, %2, %3;" : "=l"(d) : "l"(a), "l"(b), "l"(c));
    return d;
}
__device__ __forceinline__ void unpack2(unsigned long long v, float& lo, float& hi) {
    asm("mov.b64 {%0, %1}, %2;" : "=f"(lo), "=f"(hi) : "l"(v));
}

__global__ __launch_bounds__(TPB, 5)
void lightwin_kernel(const float2* __restrict__ x, const int* __restrict__ buckets,
                     const float* __restrict__ W2, const float* __restrict__ b2v,
                     const float* __restrict__ Wh, const float* __restrict__ bh,
                     float* __restrict__ out, int B, int nchunks) {
    __shared__ unsigned sVh[NB * VSTH];              // V = Wh @ W2^T, half2 pairs
    __shared__ float sc[NB];                         // c[b] = bh[b] + b2 . Wh[b]
    // staging for fused precompute (coalesced loads; bank-aware strides)
    __shared__ float sW2[HID * W2ST];
    __shared__ float sWh[NB * HALFD];
    __shared__ float sB2[HALFD];
    __shared__ float sBh[NB];

    int tid = threadIdx.x;

    // ---- stage 1: coalesced global -> smem (paid once per persistent block)
    for (int i = tid; i < HID * HALFD; i += TPB)
        sW2[(i >> 4) * W2ST + (i & 15)] = W2[i];
    for (int i = tid; i < NB * HALFD; i += TPB)
        sWh[i] = Wh[i];
    if (tid < HALFD)       sB2[tid] = b2v[tid];
    if (tid < NB)          sBh[tid] = bh[tid];
    __syncthreads();

    // ---- stage 2: combined head weights V (half2) + folded bias c
    for (int e = tid; e < NB * JJ; e += TPB) {
        int b = e >> 4, jj = e & 15;
        const float* whp = &sWh[b * HALFD];
        const float* wa  = &sW2[(2 * jj)     * W2ST];
        const float* wb  = &sW2[(2 * jj + 1) * W2ST];
        float s0 = 0.f, s1 = 0.f;
        #pragma unroll
        for (int k = 0; k < HALFD; k++) {
            float wh = whp[k];
            s0 = fmaf(wa[k], wh, s0);
            s1 = fmaf(wb[k], wh, s1);
        }
        __half2 h = __floats2half2_rn(s0, s1);
        sVh[b * VSTH + jj] = *reinterpret_cast<unsigned*>(&h);
    }
    for (int b = tid; b < NB; b += TPB) {
        float s = sBh[b];
        #pragma unroll
        for (int k = 0; k < HALFD; k++)
            s = fmaf(sB2[k], sWh[b * HALFD + k], s);
        sc[b] = s;
    }
    __syncthreads();

    // ---- stage 3: persistent block-stride loop over 1024-row chunks
    for (int ch = blockIdx.x; ch < nchunks; ch += NBLK) {
        int base = ch * CHROWS + tid;

        unsigned long long x0d[CR], x1d[CR];
        float acc0[CR], acc1[CR];
        int   va[CR];

        #pragma unroll
        for (int r = 0; r < CR; r++) {
            int idx = base + r * TPB;
            bool p = idx < B;
            float2 xv = p ? __ldg(&x[idx]) : make_float2(0.f, 0.f);
            int b = p ? buckets[idx] : 0;
            b = ((unsigned)b < NB) ? b : (NB - 1);
            va[r]   = b * VSTH;
            x0d[r]  = pack2(xv.x, xv.x);
            x1d[r]  = pack2(xv.y, xv.y);
            acc0[r] = sc[b];           // head bias folded into accumulator
            acc1[r] = 0.f;
        }

        #pragma unroll
        for (int jj = 0; jj < JJ; jj++) {
            // warp-uniform weight pairs from constant bank (LDCU, uniform port)
            unsigned long long a2  = pack2(cW1[2 * jj],       cW1[2 * jj + 1]);
            unsigned long long b2w = pack2(cW1[HID + 2 * jj], cW1[HID + 2 * jj + 1]);
            unsigned long long c2  = pack2(cB1[2 * jj],       cB1[2 * jj + 1]);
            #pragma unroll
            for (int r = 0; r < CR; r++) {
                unsigned long long z = fma2(x1d[r], b2w, c2);
                z = fma2(x0d[r], a2, z);
                float z0, z1;
                unpack2(z, z0, z1);
                float h0 = fmaxf(z0, 0.f);
                float h1 = fmaxf(z1, 0.f);
                unsigned vh = sVh[va[r] + jj];     // one LDS.32 = both fp16 weights
                float2 vf = __half22float2(*reinterpret_cast<__half2*>(&vh));
                acc0[r] = fmaf(h0, vf.x, acc0[r]);
                acc1[r] = fmaf(h1, vf.y, acc1[r]);
            }
        }

        #pragma unroll
        for (int r = 0; r < CR; r++) {
            int idx = base + r * TPB;
            if (idx < B) out[idx] = acc0[r] + acc1[r];
        }
    }
}

extern "C" void kernel_launch(void* const* d_in, const int* in_sizes, int n_in,
                              void* d_out, int out_size) {
    const float2* x     = (const float2*)d_in[0];
    const int* buckets  = (const int*)d_in[1];
    const float* W1     = (const float*)d_in[2];
    const float* b1     = (const float*)d_in[3];
    const float* W2     = (const float*)d_in[4];
    const float* b2v    = (const float*)d_in[5];
    const float* Wh     = (const float*)d_in[6];
    const float* bh     = (const float*)d_in[7];
    float* out          = (float*)d_out;

    int B = in_sizes[1];  // buckets element count = row count

    // Device-to-device async copies into constant bank (graph-capturable, no alloc)
    cudaMemcpyToSymbolAsync(cW1, W1, HID * 2 * sizeof(float), 0, cudaMemcpyDeviceToDevice);
    cudaMemcpyToSymbolAsync(cB1, b1, HID * sizeof(float), 0, cudaMemcpyDeviceToDevice);

    int nchunks = (B + CHROWS - 1) / CHROWS;   // 1954
    int grid = NBLK < nchunks ? NBLK : nchunks;
    lightwin_kernel<<<grid, TPB>>>(x, buckets, W2, b2v, Wh, bh, out, B, nchunks);
}